// round 3
// baseline (speedup 1.0000x reference)
#include <cuda_runtime.h>
#include <cuda_bf16.h>
#include <math.h>

// Problem dims (fixed by the dataset)
#define B 32
#define S 2048
#define D 1024
#define K 10
#define NCHUNK 64              // s-chunks for partial mean
#define SCHUNK (S / NCHUNK)    // 32 rows per chunk
#define D4 (D / 4)             // 256 float4 per row

#define ALPHA_BASE 0.3f
#define MAX_DELTA 0.5f
#define EPS_WHITEN 1e-8f
#define EPS_NORM 1e-8f
#define EPS_FNORM 1e-12f

// Scratch (device globals -> no allocation)
__device__ float g_partial[B * NCHUNK * D];  // 8 MB
__device__ float g_vraw[B * D];              // 128 KB
__device__ float g_corr[B * D];              // 128 KB

__device__ __forceinline__ void stcs4(float4* p, float4 v) {
    asm volatile("st.global.cs.v4.f32 [%0], {%1,%2,%3,%4};"
                 :: "l"(p), "f"(v.x), "f"(v.y), "f"(v.z), "f"(v.w) : "memory");
}

// ---------------------------------------------------------------------------
// Kernel 1: partial sums over sequence chunks. grid = (NCHUNK, B), 256 thr.
// Default-caching loads: the tail of hidden stays resident in L2 so the
// reverse-ordered k_add can hit on it.
// ---------------------------------------------------------------------------
__global__ void k_partial(const float* __restrict__ h) {
    int chunk = blockIdx.x;
    int b = blockIdx.y;
    int t = threadIdx.x;  // 0..255 -> float4 index in D
    const float4* hp = reinterpret_cast<const float4*>(h)
                       + (size_t)(b * S + chunk * SCHUNK) * D4 + t;
    float ax = 0.f, ay = 0.f, az = 0.f, aw = 0.f;
#pragma unroll 8
    for (int s = 0; s < SCHUNK; s++) {
        float4 v = __ldg(hp + (size_t)s * D4);
        ax += v.x; ay += v.y; az += v.z; aw += v.w;
    }
    reinterpret_cast<float4*>(g_partial)[(b * NCHUNK + chunk) * D4 + t] =
        make_float4(ax, ay, az, aw);
}

// ---------------------------------------------------------------------------
// Kernel 2: reduce chunks -> v_raw (mean over S). grid = B, 256 thr.
// ---------------------------------------------------------------------------
__global__ void k_finalize(void) {
    int b = blockIdx.x;
    int t = threadIdx.x;
    float ax = 0.f, ay = 0.f, az = 0.f, aw = 0.f;
#pragma unroll 8
    for (int c = 0; c < NCHUNK; c++) {
        float4 v = reinterpret_cast<const float4*>(g_partial)[(b * NCHUNK + c) * D4 + t];
        ax += v.x; ay += v.y; az += v.z; aw += v.w;
    }
    const float inv = 1.0f / (float)S;
    reinterpret_cast<float4*>(g_vraw)[b * D4 + t] =
        make_float4(ax * inv, ay * inv, az * inv, aw * inv);
}

// ---------------------------------------------------------------------------
// Kernel 3: per-batch snap. grid = B, 256 threads (each thread owns 4 d's).
// ---------------------------------------------------------------------------
__device__ __forceinline__ float warp_sum(float x) {
#pragma unroll
    for (int o = 16; o > 0; o >>= 1) x += __shfl_down_sync(0xffffffffu, x, o);
    return x;
}

__device__ __forceinline__ void block_reduce10(const float* v, float (*red)[8],
                                               float* out, int lane, int wid,
                                               int t) {
#pragma unroll
    for (int k = 0; k < K; k++) {
        float x = warp_sum(v[k]);
        if (lane == 0) red[k][wid] = x;
    }
    __syncthreads();
    if (t < K) {
        float s = 0.f;
#pragma unroll
        for (int j = 0; j < 8; j++) s += red[t][j];
        out[t] = s;
    }
    __syncthreads();
}

__global__ void k_snap(const float* __restrict__ attractors) {
    __shared__ float red[K][8];
    __shared__ float ss1S[K];
    __shared__ float ss2S[K];
    __shared__ float cosS[K];
    __shared__ float inv1S[K];
    __shared__ float bestScoreS;
    __shared__ int bestIdxS;

    int b = blockIdx.x;
    int t = threadIdx.x;
    int lane = t & 31, wid = t >> 5;

    const float4* vr4 = reinterpret_cast<const float4*>(g_vraw);

    // whitening stats over the batch for this thread's 4 d's
    float4 sum = make_float4(0, 0, 0, 0), ssq = make_float4(0, 0, 0, 0);
    float4 vrb = make_float4(0, 0, 0, 0);
#pragma unroll 4
    for (int bb = 0; bb < B; bb++) {
        float4 v = __ldg(vr4 + bb * D4 + t);
        sum.x += v.x; sum.y += v.y; sum.z += v.z; sum.w += v.w;
        ssq.x += v.x * v.x; ssq.y += v.y * v.y;
        ssq.z += v.z * v.z; ssq.w += v.w * v.w;
        if (bb == b) vrb = v;
    }
    const float invB = 1.0f / (float)B;
    float4 mean = make_float4(sum.x * invB, sum.y * invB, sum.z * invB, sum.w * invB);
    float4 var = make_float4(ssq.x * invB - mean.x * mean.x,
                             ssq.y * invB - mean.y * mean.y,
                             ssq.z * invB - mean.z * mean.z,
                             ssq.w * invB - mean.w * mean.w);
    float4 rstd = make_float4(rsqrtf(var.x + EPS_WHITEN), rsqrtf(var.y + EPS_WHITEN),
                              rsqrtf(var.z + EPS_WHITEN), rsqrtf(var.w + EPS_WHITEN));
    float4 vn = make_float4((vrb.x - mean.x) * rstd.x, (vrb.y - mean.y) * rstd.y,
                            (vrb.z - mean.z) * rstd.z, (vrb.w - mean.w) * rstd.w);

    // attractor normalization
    const float4* a4p = reinterpret_cast<const float4*>(attractors);
    float4 a[K];
    float acc[K];
#pragma unroll
    for (int k = 0; k < K; k++) {
        a[k] = __ldg(a4p + k * D4 + t);
        acc[k] = a[k].x * a[k].x + a[k].y * a[k].y + a[k].z * a[k].z + a[k].w * a[k].w;
    }
    block_reduce10(acc, red, ss1S, lane, wid, t);
    if (t < K) inv1S[t] = 1.0f / fmaxf(sqrtf(ss1S[t]), EPS_NORM);
    __syncthreads();

#pragma unroll
    for (int k = 0; k < K; k++) {
        float s1 = inv1S[k];
        a[k].x *= s1; a[k].y *= s1; a[k].z *= s1; a[k].w *= s1;
        acc[k] = a[k].x * a[k].x + a[k].y * a[k].y + a[k].z * a[k].z + a[k].w * a[k].w;
    }
    block_reduce10(acc, red, ss2S, lane, wid, t);

#pragma unroll
    for (int k = 0; k < K; k++) {
        float s2 = 1.0f / fmaxf(sqrtf(ss2S[k]), EPS_FNORM);
        acc[k] = vn.x * (a[k].x * s2) + vn.y * (a[k].y * s2) +
                 vn.z * (a[k].z * s2) + vn.w * (a[k].w * s2);
    }
    block_reduce10(acc, red, cosS, lane, wid, t);

    if (t == 0) {
        float best = cosS[0];
        int bi = 0;
#pragma unroll
        for (int k = 1; k < K; k++) {
            if (cosS[k] > best) { best = cosS[k]; bi = k; }
        }
        bestScoreS = best;
        bestIdxS = bi;
    }
    __syncthreads();

    float alpha = ALPHA_BASE * (1.0f - bestScoreS);
    int bi = bestIdxS;
    float s1 = inv1S[bi];
    float4 craw = __ldg(a4p + bi * D4 + t);
    float cx = craw.x * s1, cy = craw.y * s1, cz = craw.z * s1, cw = craw.w * s1;

    float dx = fminf(fmaxf(cx - vn.x, -MAX_DELTA), MAX_DELTA);
    float dy = fminf(fmaxf(cy - vn.y, -MAX_DELTA), MAX_DELTA);
    float dz = fminf(fmaxf(cz - vn.z, -MAX_DELTA), MAX_DELTA);
    float dw = fminf(fmaxf(cw - vn.w, -MAX_DELTA), MAX_DELTA);

    reinterpret_cast<float4*>(g_corr)[b * D4 + t] =
        make_float4(vn.x + alpha * dx - vrb.x,
                    vn.y + alpha * dy - vrb.y,
                    vn.z + alpha * dz - vrb.z,
                    vn.w + alpha * dw - vrb.w);
}

// ---------------------------------------------------------------------------
// Kernel 4: out = hidden + correction[b][d]   (the big 512 MB pass)
// REVERSE streaming order: pass 1 read hidden in ascending address order, so
// the tail of hidden is L2-resident when this kernel starts. We touch the
// highest addresses first (8 MB per grid-wave) to harvest those hits, and
// stream the output with evict-first stores so writes don't pollute L2.
// total/stride = 32 exactly, so no bounds checks are needed.
// ---------------------------------------------------------------------------
__global__ void k_add(const float* __restrict__ h, float* __restrict__ out) {
    const float4* h4 = reinterpret_cast<const float4*>(h);
    float4* o4 = reinterpret_cast<float4*>(out);
    const float4* c4 = reinterpret_cast<const float4*>(g_corr);
    const int total = B * S * D4;              // 16,777,216 float4
    const int stride = gridDim.x * blockDim.x; // 524,288 (divides total 32x)
    const int idx = blockIdx.x * blockDim.x + threadIdx.x;
    const int niter = total / stride;          // 32
#pragma unroll 4
    for (int n = 0; n < niter; n++) {
        int i = total - (n + 1) * stride + idx;  // descending 8 MB waves
        float4 hv = __ldg(h4 + i);
        float4 cv = __ldg(c4 + ((i >> 19) << 8) + (i & (D4 - 1)));
        stcs4(o4 + i, make_float4(hv.x + cv.x, hv.y + cv.y, hv.z + cv.z, hv.w + cv.w));
    }
}

// ---------------------------------------------------------------------------
extern "C" void kernel_launch(void* const* d_in, const int* in_sizes, int n_in,
                              void* d_out, int out_size) {
    const float* hidden = (const float*)d_in[0];      // [B, S, D]
    const float* attractors = (const float*)d_in[1];  // [K, D]
    float* out = (float*)d_out;
    (void)in_sizes; (void)n_in; (void)out_size;

    dim3 g1(NCHUNK, B);
    k_partial<<<g1, 256>>>(hidden);
    k_finalize<<<B, 256>>>();
    k_snap<<<B, 256>>>(attractors);
    k_add<<<2048, 256>>>(hidden, out);
}

// round 6
// speedup vs baseline: 1.0839x; 1.0839x over previous
#include <cuda_runtime.h>
#include <cuda_bf16.h>
#include <math.h>

// Problem dims (fixed by the dataset)
#define B 32
#define S 2048
#define D 1024
#define K 10
#define NCHUNK 16              // s-chunks for partial mean
#define SCHUNK (S / NCHUNK)    // 128 rows per chunk
#define D4 (D / 4)             // 256 float4 per row

#define ALPHA_BASE 0.3f
#define MAX_DELTA 0.5f
#define EPS_WHITEN 1e-8f
#define EPS_NORM 1e-8f
#define EPS_FNORM 1e-12f

// Scratch (device globals -> no allocation)
__device__ float g_partial[B * NCHUNK * D];  // 2 MB
__device__ float g_vraw[B * D];              // 128 KB
__device__ float g_corr[B * D];              // 128 KB

// ---------------------------------------------------------------------------
// Kernel 1: partial sums over sequence chunks. grid = (NCHUNK, B), 256 thr.
// Each thread owns one float4 column slice, sums 128 rows. (R1-proven)
// ---------------------------------------------------------------------------
__global__ void k_partial(const float* __restrict__ h) {
    int chunk = blockIdx.x;
    int b = blockIdx.y;
    int t = threadIdx.x;  // 0..255 -> float4 index in D
    const float4* hp = reinterpret_cast<const float4*>(h)
                       + (size_t)(b * S + chunk * SCHUNK) * D4 + t;
    float ax = 0.f, ay = 0.f, az = 0.f, aw = 0.f;
#pragma unroll 8
    for (int s = 0; s < SCHUNK; s++) {
        float4 v = __ldg(hp + (size_t)s * D4);
        ax += v.x; ay += v.y; az += v.z; aw += v.w;
    }
    reinterpret_cast<float4*>(g_partial)[(b * NCHUNK + chunk) * D4 + t] =
        make_float4(ax, ay, az, aw);
}

// ---------------------------------------------------------------------------
// Kernel 2: reduce chunks -> v_raw (mean over S). grid = B, 256 thr.
// ---------------------------------------------------------------------------
__global__ void k_finalize(void) {
    int b = blockIdx.x;
    int t = threadIdx.x;
    float ax = 0.f, ay = 0.f, az = 0.f, aw = 0.f;
#pragma unroll
    for (int c = 0; c < NCHUNK; c++) {
        float4 v = reinterpret_cast<const float4*>(g_partial)[(b * NCHUNK + c) * D4 + t];
        ax += v.x; ay += v.y; az += v.z; aw += v.w;
    }
    const float inv = 1.0f / (float)S;
    reinterpret_cast<float4*>(g_vraw)[b * D4 + t] =
        make_float4(ax * inv, ay * inv, az * inv, aw * inv);
}

// ---------------------------------------------------------------------------
// Kernel 3: per-batch snap. grid = B, 256 threads (each thread owns 4 d's).
// ---------------------------------------------------------------------------
__device__ __forceinline__ float warp_sum(float x) {
#pragma unroll
    for (int o = 16; o > 0; o >>= 1) x += __shfl_down_sync(0xffffffffu, x, o);
    return x;
}

__device__ __forceinline__ void block_reduce10(const float* v, float (*red)[8],
                                               float* out, int lane, int wid,
                                               int t) {
#pragma unroll
    for (int k = 0; k < K; k++) {
        float x = warp_sum(v[k]);
        if (lane == 0) red[k][wid] = x;
    }
    __syncthreads();
    if (t < K) {
        float s = 0.f;
#pragma unroll
        for (int j = 0; j < 8; j++) s += red[t][j];
        out[t] = s;
    }
    __syncthreads();
}

__global__ void k_snap(const float* __restrict__ attractors) {
    __shared__ float red[K][8];
    __shared__ float ss1S[K];
    __shared__ float ss2S[K];
    __shared__ float cosS[K];
    __shared__ float inv1S[K];
    __shared__ float bestScoreS;
    __shared__ int bestIdxS;

    int b = blockIdx.x;
    int t = threadIdx.x;
    int lane = t & 31, wid = t >> 5;

    const float4* vr4 = reinterpret_cast<const float4*>(g_vraw);

    // whitening stats over the batch for this thread's 4 d's
    float4 sum = make_float4(0, 0, 0, 0), ssq = make_float4(0, 0, 0, 0);
    float4 vrb = make_float4(0, 0, 0, 0);
#pragma unroll 4
    for (int bb = 0; bb < B; bb++) {
        float4 v = __ldg(vr4 + bb * D4 + t);
        sum.x += v.x; sum.y += v.y; sum.z += v.z; sum.w += v.w;
        ssq.x += v.x * v.x; ssq.y += v.y * v.y;
        ssq.z += v.z * v.z; ssq.w += v.w * v.w;
        if (bb == b) vrb = v;
    }
    const float invB = 1.0f / (float)B;
    float4 mean = make_float4(sum.x * invB, sum.y * invB, sum.z * invB, sum.w * invB);
    float4 var = make_float4(ssq.x * invB - mean.x * mean.x,
                             ssq.y * invB - mean.y * mean.y,
                             ssq.z * invB - mean.z * mean.z,
                             ssq.w * invB - mean.w * mean.w);
    float4 rstd = make_float4(rsqrtf(var.x + EPS_WHITEN), rsqrtf(var.y + EPS_WHITEN),
                              rsqrtf(var.z + EPS_WHITEN), rsqrtf(var.w + EPS_WHITEN));
    float4 vn = make_float4((vrb.x - mean.x) * rstd.x, (vrb.y - mean.y) * rstd.y,
                            (vrb.z - mean.z) * rstd.z, (vrb.w - mean.w) * rstd.w);

    // attractor normalization
    const float4* a4p = reinterpret_cast<const float4*>(attractors);
    float4 a[K];
    float acc[K];
#pragma unroll
    for (int k = 0; k < K; k++) {
        a[k] = __ldg(a4p + k * D4 + t);
        acc[k] = a[k].x * a[k].x + a[k].y * a[k].y + a[k].z * a[k].z + a[k].w * a[k].w;
    }
    block_reduce10(acc, red, ss1S, lane, wid, t);
    if (t < K) inv1S[t] = 1.0f / fmaxf(sqrtf(ss1S[t]), EPS_NORM);
    __syncthreads();

#pragma unroll
    for (int k = 0; k < K; k++) {
        float s1 = inv1S[k];
        a[k].x *= s1; a[k].y *= s1; a[k].z *= s1; a[k].w *= s1;
        acc[k] = a[k].x * a[k].x + a[k].y * a[k].y + a[k].z * a[k].z + a[k].w * a[k].w;
    }
    block_reduce10(acc, red, ss2S, lane, wid, t);

#pragma unroll
    for (int k = 0; k < K; k++) {
        float s2 = 1.0f / fmaxf(sqrtf(ss2S[k]), EPS_FNORM);
        acc[k] = vn.x * (a[k].x * s2) + vn.y * (a[k].y * s2) +
                 vn.z * (a[k].z * s2) + vn.w * (a[k].w * s2);
    }
    block_reduce10(acc, red, cosS, lane, wid, t);

    if (t == 0) {
        float best = cosS[0];
        int bi = 0;
#pragma unroll
        for (int k = 1; k < K; k++) {
            if (cosS[k] > best) { best = cosS[k]; bi = k; }
        }
        bestScoreS = best;
        bestIdxS = bi;
    }
    __syncthreads();

    float alpha = ALPHA_BASE * (1.0f - bestScoreS);
    int bi = bestIdxS;
    float s1 = inv1S[bi];
    float4 craw = __ldg(a4p + bi * D4 + t);
    float cx = craw.x * s1, cy = craw.y * s1, cz = craw.z * s1, cw = craw.w * s1;

    float dx = fminf(fmaxf(cx - vn.x, -MAX_DELTA), MAX_DELTA);
    float dy = fminf(fmaxf(cy - vn.y, -MAX_DELTA), MAX_DELTA);
    float dz = fminf(fmaxf(cz - vn.z, -MAX_DELTA), MAX_DELTA);
    float dw = fminf(fmaxf(cw - vn.w, -MAX_DELTA), MAX_DELTA);

    reinterpret_cast<float4*>(g_corr)[b * D4 + t] =
        make_float4(vn.x + alpha * dx - vrb.x,
                    vn.y + alpha * dy - vrb.y,
                    vn.z + alpha * dz - vrb.z,
                    vn.w + alpha * dw - vrb.w);
}

// ---------------------------------------------------------------------------
// Kernel 4: out = hidden + correction[b][d]  — tiled for burst RW.
// Tile = 1024 float4 (16 KB), contiguous, never crosses a batch boundary
// (1024 | 524288). Within a tile, thread t's 4 elements all have column t and
// the same b => ONE corr load per tile, zero per-load index math.
// 4 independent loads then 4 stores per tile: longer read bursts cut DRAM
// read<->write turnaround.
// ---------------------------------------------------------------------------
__global__ void k_add(const float* __restrict__ h, float* __restrict__ out) {
    const float4* __restrict__ h4 = reinterpret_cast<const float4*>(h);
    float4* __restrict__ o4 = reinterpret_cast<float4*>(out);
    const float4* __restrict__ c4 = reinterpret_cast<const float4*>(g_corr);
    const int ntiles = (B * S * D4) / 1024;  // 16384
    const int t = threadIdx.x;               // 0..255 == column id
    for (int tile = blockIdx.x; tile < ntiles; tile += gridDim.x) {
        int b = tile >> 9;  // 512 tiles per batch
        const float4* hp = h4 + (size_t)tile * 1024 + t;
        float4* op = o4 + (size_t)tile * 1024 + t;
        float4 c = __ldg(c4 + (b << 8) + t);
        float4 v0 = __ldg(hp);
        float4 v1 = __ldg(hp + 256);
        float4 v2 = __ldg(hp + 512);
        float4 v3 = __ldg(hp + 768);
        op[0]   = make_float4(v0.x + c.x, v0.y + c.y, v0.z + c.z, v0.w + c.w);
        op[256] = make_float4(v1.x + c.x, v1.y + c.y, v1.z + c.z, v1.w + c.w);
        op[512] = make_float4(v2.x + c.x, v2.y + c.y, v2.z + c.z, v2.w + c.w);
        op[768] = make_float4(v3.x + c.x, v3.y + c.y, v3.z + c.z, v3.w + c.w);
    }
}

// ---------------------------------------------------------------------------
extern "C" void kernel_launch(void* const* d_in, const int* in_sizes, int n_in,
                              void* d_out, int out_size) {
    const float* hidden = (const float*)d_in[0];      // [B, S, D]
    const float* attractors = (const float*)d_in[1];  // [K, D]
    float* out = (float*)d_out;
    (void)in_sizes; (void)n_in; (void)out_size;

    dim3 g1(NCHUNK, B);
    k_partial<<<g1, 256>>>(hidden);
    k_finalize<<<B, 256>>>();
    k_snap<<<B, 256>>>(attractors);
    k_add<<<2048, 256>>>(hidden, out);
}

// round 7
// speedup vs baseline: 1.1006x; 1.0154x over previous
#include <cuda_runtime.h>
#include <cuda_bf16.h>
#include <math.h>

// Problem dims (fixed by the dataset)
#define B 32
#define S 2048
#define D 1024
#define K 10
#define NCHUNK 16              // s-chunks for partial mean
#define SCHUNK (S / NCHUNK)    // 128 rows per chunk
#define D4 (D / 4)             // 256 float4 per row

#define ALPHA_BASE 0.3f
#define MAX_DELTA 0.5f
#define EPS_WHITEN 1e-8f
#define EPS_NORM 1e-8f
#define EPS_FNORM 1e-12f

// Scratch (device globals -> no allocation)
__device__ float g_partial[B * NCHUNK * D];  // 2 MB
__device__ float g_vraw[B * D];              // 128 KB
__device__ float g_mean[D];                  // 4 KB
__device__ float g_rstd[D];                  // 4 KB
__device__ float g_corr[B * D];              // 128 KB

// ---------------------------------------------------------------------------
// Kernel 1: partial sums over sequence chunks. grid = (NCHUNK, B), 256 thr.
// (R1/R6-proven; do not touch)
// ---------------------------------------------------------------------------
__global__ void k_partial(const float* __restrict__ h) {
    int chunk = blockIdx.x;
    int b = blockIdx.y;
    int t = threadIdx.x;  // 0..255 -> float4 index in D
    const float4* hp = reinterpret_cast<const float4*>(h)
                       + (size_t)(b * S + chunk * SCHUNK) * D4 + t;
    float ax = 0.f, ay = 0.f, az = 0.f, aw = 0.f;
#pragma unroll 8
    for (int s = 0; s < SCHUNK; s++) {
        float4 v = __ldg(hp + (size_t)s * D4);
        ax += v.x; ay += v.y; az += v.z; aw += v.w;
    }
    reinterpret_cast<float4*>(g_partial)[(b * NCHUNK + chunk) * D4 + t] =
        make_float4(ax, ay, az, aw);
}

// ---------------------------------------------------------------------------
// Kernel 2 (fused finalize + whitening stats). grid = 32 blocks, 256 thr.
// Thread layout: warp w owns float4-column c = blockIdx.x*8 + w, lane = batch.
// Each thread reduces the 16 chunks for its (b, c) -> v_raw, then the warp
// (lanes = all 32 batches of one column) shuffle-reduces mean/var per dim.
// All traffic is L2 (2 MB in, 136 KB out).
// ---------------------------------------------------------------------------
__device__ __forceinline__ float warp_allsum(float x) {
#pragma unroll
    for (int o = 16; o > 0; o >>= 1) x += __shfl_xor_sync(0xffffffffu, x, o);
    return x;
}

__global__ void k_stats(void) {
    int lane = threadIdx.x & 31;   // = batch b
    int w = threadIdx.x >> 5;      // 0..7
    int c = blockIdx.x * 8 + w;    // float4 column 0..255
    int b = lane;

    const float4* p4 = reinterpret_cast<const float4*>(g_partial);
    float ax = 0.f, ay = 0.f, az = 0.f, aw = 0.f;
#pragma unroll
    for (int ch = 0; ch < NCHUNK; ch++) {
        float4 v = p4[(b * NCHUNK + ch) * D4 + c];
        ax += v.x; ay += v.y; az += v.z; aw += v.w;
    }
    const float invS = 1.0f / (float)S;
    float4 vr = make_float4(ax * invS, ay * invS, az * invS, aw * invS);
    reinterpret_cast<float4*>(g_vraw)[b * D4 + c] = vr;

    // cross-batch mean / var (ddof=0) per component, via full-warp reduce
    const float invB = 1.0f / (float)B;
    float mx = warp_allsum(vr.x) * invB;
    float my = warp_allsum(vr.y) * invB;
    float mz = warp_allsum(vr.z) * invB;
    float mw = warp_allsum(vr.w) * invB;
    float qx = warp_allsum(vr.x * vr.x) * invB - mx * mx;
    float qy = warp_allsum(vr.y * vr.y) * invB - my * my;
    float qz = warp_allsum(vr.z * vr.z) * invB - mz * mz;
    float qw = warp_allsum(vr.w * vr.w) * invB - mw * mw;
    if (lane == 0) {
        reinterpret_cast<float4*>(g_mean)[c] = make_float4(mx, my, mz, mw);
        reinterpret_cast<float4*>(g_rstd)[c] =
            make_float4(rsqrtf(qx + EPS_WHITEN), rsqrtf(qy + EPS_WHITEN),
                        rsqrtf(qz + EPS_WHITEN), rsqrtf(qw + EPS_WHITEN));
    }
}

// ---------------------------------------------------------------------------
// Kernel 3: per-batch snap. grid = B, 256 threads. One fused 20-value block
// reduction (Σa_k² and Σvn·a_k); cos/argmax derived algebraically:
//   inv1 = 1/max(sqrt(ss1), EPS_NORM);  n2 = sqrt(ss1)*inv1
//   inv2 = 1/max(n2, EPS_FNORM);        cos = dot*inv1*inv2
// ---------------------------------------------------------------------------
__device__ __forceinline__ float warp_sum(float x) {
#pragma unroll
    for (int o = 16; o > 0; o >>= 1) x += __shfl_down_sync(0xffffffffu, x, o);
    return x;
}

__global__ void k_snap(const float* __restrict__ attractors) {
    __shared__ float red[2 * K][8];
    __shared__ float sums[2 * K];   // [0..K): ss1, [K..2K): dot
    __shared__ float alphaS, s1bS;
    __shared__ int bestIdxS;

    int b = blockIdx.x;
    int t = threadIdx.x;
    int lane = t & 31, wid = t >> 5;

    float4 vrb = reinterpret_cast<const float4*>(g_vraw)[b * D4 + t];
    float4 mean = reinterpret_cast<const float4*>(g_mean)[t];
    float4 rstd = reinterpret_cast<const float4*>(g_rstd)[t];
    float4 vn = make_float4((vrb.x - mean.x) * rstd.x, (vrb.y - mean.y) * rstd.y,
                            (vrb.z - mean.z) * rstd.z, (vrb.w - mean.w) * rstd.w);

    const float4* a4p = reinterpret_cast<const float4*>(attractors);
    float acc[2 * K];
#pragma unroll
    for (int k = 0; k < K; k++) {
        float4 a = __ldg(a4p + k * D4 + t);
        acc[k]     = a.x * a.x + a.y * a.y + a.z * a.z + a.w * a.w;
        acc[K + k] = vn.x * a.x + vn.y * a.y + vn.z * a.z + vn.w * a.w;
    }
#pragma unroll
    for (int j = 0; j < 2 * K; j++) {
        float x = warp_sum(acc[j]);
        if (lane == 0) red[j][wid] = x;
    }
    __syncthreads();
    if (t < 2 * K) {
        float s = 0.f;
#pragma unroll
        for (int j = 0; j < 8; j++) s += red[t][j];
        sums[t] = s;
    }
    __syncthreads();

    if (t == 0) {
        float best = -1e30f, s1b = 0.f;
        int bi = 0;
#pragma unroll
        for (int k = 0; k < K; k++) {
            float n1 = sqrtf(sums[k]);
            float s1 = 1.0f / fmaxf(n1, EPS_NORM);
            float n2 = n1 * s1;                       // ||att|| after first normalize
            float s2 = 1.0f / fmaxf(n2, EPS_FNORM);
            float cosk = sums[K + k] * s1 * s2;
            if (cosk > best) { best = cosk; bi = k; s1b = s1; }
        }
        bestIdxS = bi;
        s1bS = s1b;
        alphaS = ALPHA_BASE * (1.0f - best);
    }
    __syncthreads();

    float alpha = alphaS;
    float s1 = s1bS;
    float4 craw = __ldg(a4p + bestIdxS * D4 + t);
    float cx = craw.x * s1, cy = craw.y * s1, cz = craw.z * s1, cw = craw.w * s1;

    float dx = fminf(fmaxf(cx - vn.x, -MAX_DELTA), MAX_DELTA);
    float dy = fminf(fmaxf(cy - vn.y, -MAX_DELTA), MAX_DELTA);
    float dz = fminf(fmaxf(cz - vn.z, -MAX_DELTA), MAX_DELTA);
    float dw = fminf(fmaxf(cw - vn.w, -MAX_DELTA), MAX_DELTA);

    reinterpret_cast<float4*>(g_corr)[b * D4 + t] =
        make_float4(vn.x + alpha * dx - vrb.x,
                    vn.y + alpha * dy - vrb.y,
                    vn.z + alpha * dz - vrb.z,
                    vn.w + alpha * dw - vrb.w);
}

// ---------------------------------------------------------------------------
// Kernel 4: out = hidden + correction[b][d]  — tiled burst RW (R6-proven).
// ---------------------------------------------------------------------------
__global__ void k_add(const float* __restrict__ h, float* __restrict__ out) {
    const float4* __restrict__ h4 = reinterpret_cast<const float4*>(h);
    float4* __restrict__ o4 = reinterpret_cast<float4*>(out);
    const float4* __restrict__ c4 = reinterpret_cast<const float4*>(g_corr);
    const int ntiles = (B * S * D4) / 1024;  // 16384
    const int t = threadIdx.x;               // 0..255 == column id
    for (int tile = blockIdx.x; tile < ntiles; tile += gridDim.x) {
        int b = tile >> 9;  // 512 tiles per batch
        const float4* hp = h4 + (size_t)tile * 1024 + t;
        float4* op = o4 + (size_t)tile * 1024 + t;
        float4 c = __ldg(c4 + (b << 8) + t);
        float4 v0 = __ldg(hp);
        float4 v1 = __ldg(hp + 256);
        float4 v2 = __ldg(hp + 512);
        float4 v3 = __ldg(hp + 768);
        op[0]   = make_float4(v0.x + c.x, v0.y + c.y, v0.z + c.z, v0.w + c.w);
        op[256] = make_float4(v1.x + c.x, v1.y + c.y, v1.z + c.z, v1.w + c.w);
        op[512] = make_float4(v2.x + c.x, v2.y + c.y, v2.z + c.z, v2.w + c.w);
        op[768] = make_float4(v3.x + c.x, v3.y + c.y, v3.z + c.z, v3.w + c.w);
    }
}

// ---------------------------------------------------------------------------
extern "C" void kernel_launch(void* const* d_in, const int* in_sizes, int n_in,
                              void* d_out, int out_size) {
    const float* hidden = (const float*)d_in[0];      // [B, S, D]
    const float* attractors = (const float*)d_in[1];  // [K, D]
    float* out = (float*)d_out;
    (void)in_sizes; (void)n_in; (void)out_size;

    dim3 g1(NCHUNK, B);
    k_partial<<<g1, 256>>>(hidden);
    k_stats<<<32, 256>>>();
    k_snap<<<B, 256>>>(attractors);
    k_add<<<2048, 256>>>(hidden, out);
}